// round 2
// baseline (speedup 1.0000x reference)
#include <cuda_runtime.h>
#include <math.h>

#define DS   128
#define DSM  (DS - 1)
#define D3   (DS * DS * DS)

// Tile: 32 x 4 x 8 real cells; 512 threads, each owns the z-pair (z, z+4).
#define TXD  32
#define TYD  4
#define TZD  8
#define TZH  4
#define NTHR (TXD * TYD * TZH)   // 512

// Halo in float2 pair-planes: pair-plane zp holds real planes (z0+zp-2, z0+zp+2)
#define HX    36
#define HY    8
#define HZP   8
#define HXY   (HX * HY)          // 288
#define HTOT2 (HX * HY * HZP)    // 2304 float2 per field

typedef unsigned long long u64;

__device__ __forceinline__ u64 pk(float a, float b) {
    u64 r; asm("mov.b64 %0, {%1,%2};" : "=l"(r) : "f"(a), "f"(b)); return r;
}
__device__ __forceinline__ void unpk(u64 v, float& a, float& b) {
    asm("mov.b64 {%0,%1}, %2;" : "=f"(a), "=f"(b) : "l"(v));
}
__device__ __forceinline__ u64 f2fma(u64 a, u64 b, u64 c) {
    u64 d; asm("fma.rn.f32x2 %0,%1,%2,%3;" : "=l"(d) : "l"(a), "l"(b), "l"(c)); return d;
}
__device__ __forceinline__ u64 f2mul(u64 a, u64 b) {
    u64 d; asm("mul.rn.f32x2 %0,%1,%2;" : "=l"(d) : "l"(a), "l"(b)); return d;
}
__device__ __forceinline__ float fast_rsqrt(float x) {
    float r; asm("rsqrt.approx.f32 %0, %1;" : "=f"(r) : "f"(x)); return r;
}

// Packed stencil contribution at float2-halo offset o.
// coef = (KN*(dist-2) + ETA*vn)/dist  ==  rcd^2*(KN*sq + ETA*vnu) - 2KN*rcd
// with rcd = 1/dist = rsqrt(sq), vnu = dv.d  (vn = vnu*rcd).
#define CONTRIB2(o)                                                          \
    {                                                                        \
        u64 sx = SX2[(o)], sy = SY2[(o)], sz = SZ2[(o)];                     \
        u64 dx = f2fma(sx, NEG1, Xp);                                        \
        u64 dy = f2fma(sy, NEG1, Yp);                                        \
        u64 dz = f2fma(sz, NEG1, Zp);                                        \
        u64 sq = f2fma(dx, dx, EPS2);                                        \
        sq = f2fma(dy, dy, sq);                                              \
        sq = f2fma(dz, dz, sq);                                              \
        float s0, s1; unpk(sq, s0, s1);                                      \
        bool p0 = s0 < 4.0f, p1 = s1 < 4.0f;                                 \
        if (p0 || p1) {                                                      \
            u64 svx = SVX2[(o)], svy = SVY2[(o)], svz = SVZ2[(o)];           \
            u64 dvx = f2fma(svx, NEG1, VXp);                                 \
            u64 dvy = f2fma(svy, NEG1, VYp);                                 \
            u64 dvz = f2fma(svz, NEG1, VZp);                                 \
            u64 vnu = f2mul(dvx, dx);                                        \
            vnu = f2fma(dvy, dy, vnu);                                       \
            vnu = f2fma(dvz, dz, vnu);                                       \
            u64 rcd = pk(fast_rsqrt(s0), fast_rsqrt(s1));                    \
        u64 rcd2 = f2mul(rcd, rcd);                                          \
            u64 a = f2fma(M2KN, rcd, KNP);                                   \
            u64 t = f2fma(ETAP, vnu, pk(0.0f, 0.0f));                        \
            u64 coef = f2fma(t, rcd2, a);                                    \
            float c0, c1; unpk(coef, c0, c1);                                \
            coef = pk(p0 ? c0 : 0.0f, p1 ? c1 : 0.0f);                       \
            fxp = f2fma(coef, dx, fxp);                                      \
            fyp = f2fma(coef, dy, fyp);                                      \
            fzp = f2fma(coef, dz, fzp);                                      \
        }                                                                    \
    }

__device__ __forceinline__ void finish_half(
    float X, float Y, float Z, float VX, float VY, float VZ,
    float m, float fx, float fy, float fz, float ETA, float* __restrict__ out)
{
    if (m == 0.0f) return;
    const float KN = 500000.0f;
    float bl = (X != 0.0f && X < 1.0f) ? 1.0f : 0.0f;
    float br = (X > 126.0f) ? 1.0f : 0.0f;
    float bb = (Y != 0.0f && Y < 1.0f) ? 1.0f : 0.0f;
    float bt = (Y > 126.0f) ? 1.0f : 0.0f;
    float bf = (Z != 0.0f && Z < 1.0f) ? 1.0f : 0.0f;
    float bk = (Z > 126.0f) ? 1.0f : 0.0f;
    float fxb = KN * bl * (1.0f - X) - KN * br * (X - 126.0f) - ETA * VX * (bl + br);
    float fyb = KN * bb * (1.0f - Y) - KN * bt * (Y - 126.0f) - ETA * VY * (bb + bt);
    float fzb = KN * bf * (1.0f - Z) - KN * bk * (Z - 126.0f) - ETA * VZ * (bf + bk);

    float vxn = VX + 1e-4f * (-fx + fxb);
    float vyn = VY + 1e-4f * (-9.8f - fy + fyb);
    float vzn = VZ + 1e-4f * (-fz + fzb);
    float xn = X + 1e-4f * vxn;
    float yn = Y + 1e-4f * vyn;
    float zn = Z + 1e-4f * vzn;

    int cx = __float2int_rn(xn);
    int cy = __float2int_rn(yn);
    int cz = __float2int_rn(zn);
    if (cx >= 1 && cx <= 127 && cy >= 1 && cy <= 127 && cz >= 1 && cz <= 127) {
        int l = (cz << 14) | (cy << 7) | cx;
        out[l]          = xn;
        out[D3 + l]     = yn;
        out[2 * D3 + l] = zn;
        out[3 * D3 + l] = vxn;
        out[4 * D3 + l] = vyn;
        out[5 * D3 + l] = vzn;
        out[6 * D3 + l] = 1.0f;
    }
}

__global__ __launch_bounds__(NTHR, 2) void dem_step(
    const float* __restrict__ xg,  const float* __restrict__ yg,
    const float* __restrict__ zg,  const float* __restrict__ vxg,
    const float* __restrict__ vyg, const float* __restrict__ vzg,
    const float* __restrict__ mg,  float* __restrict__ out, float ETA)
{
    extern __shared__ float2 sm2[];
    float2* FX2 = sm2;
    const u64* SX2  = (const u64*)(sm2);
    const u64* SY2  = (const u64*)(sm2 + HTOT2);
    const u64* SZ2  = (const u64*)(sm2 + 2 * HTOT2);
    const u64* SVX2 = (const u64*)(sm2 + 3 * HTOT2);
    const u64* SVY2 = (const u64*)(sm2 + 4 * HTOT2);
    const u64* SVZ2 = (const u64*)(sm2 + 5 * HTOT2);

    const int x0 = blockIdx.x * TXD;
    const int y0 = blockIdx.y * TYD;
    const int z0 = blockIdx.z * TZD;
    const int tid = threadIdx.x + TXD * (threadIdx.y + TYD * threadIdx.z);

    // Cooperative halo fill: pair-plane zp holds real z planes (z0+zp-2, z0+zp+2),
    // each wrapped mod 128 (periodic roll).
    for (int i = tid; i < HTOT2; i += NTHR) {
        int lx = i % HX;
        int t  = i / HX;
        int ly = t % HY;
        int zp = t / HY;
        int gx  = (x0 + lx - 2) & DSM;
        int gy  = (y0 + ly - 2) & DSM;
        int rz0 = (z0 + zp - 2) & DSM;
        int rz1 = (z0 + zp + 2) & DSM;
        int g0 = (rz0 << 14) | (gy << 7) | gx;
        int g1 = (rz1 << 14) | (gy << 7) | gx;
        FX2[i]             = make_float2(__ldg(xg + g0),  __ldg(xg + g1));
        FX2[i + HTOT2]     = make_float2(__ldg(yg + g0),  __ldg(yg + g1));
        FX2[i + 2 * HTOT2] = make_float2(__ldg(zg + g0),  __ldg(zg + g1));
        FX2[i + 3 * HTOT2] = make_float2(__ldg(vxg + g0), __ldg(vxg + g1));
        FX2[i + 4 * HTOT2] = make_float2(__ldg(vyg + g0), __ldg(vyg + g1));
        FX2[i + 5 * HTOT2] = make_float2(__ldg(vzg + g0), __ldg(vzg + g1));
    }
    __syncthreads();

    const int gx  = x0 + threadIdx.x;
    const int gy  = y0 + threadIdx.y;
    const int gz0 = z0 + threadIdx.z;          // first cell; second is gz0+4
    const float m0 = __ldg(mg + ((gz0 << 14) | (gy << 7) | gx));
    const float m1 = __ldg(mg + (((gz0 + 4) << 14) | (gy << 7) | gx));
    if (m0 == 0.0f && m1 == 0.0f) return;      // both halves empty: output stays 0

    const int c = ((threadIdx.z + 2) * HY + (threadIdx.y + 2)) * HX + (threadIdx.x + 2);
    const u64 Xp  = SX2[c],  Yp  = SY2[c],  Zp  = SZ2[c];
    const u64 VXp = SVX2[c], VYp = SVY2[c], VZp = SVZ2[c];

    const u64 NEG1 = pk(-1.0f, -1.0f);
    const u64 EPS2 = pk(1e-20f, 1e-20f);
    const u64 KNP  = pk(500000.0f, 500000.0f);
    const u64 M2KN = pk(-1000000.0f, -1000000.0f);
    const u64 ETAP = pk(ETA, ETA);

    u64 fxp = pk(0.0f, 0.0f), fyp = pk(0.0f, 0.0f), fzp = pk(0.0f, 0.0f);

    // 80 shifts with s^2 in [1,6] — only these allow contact between two
    // occupied particles (pos = idx +- 0.2). Fully unrolled: immediates.
    #pragma unroll
    for (int oz = -2; oz <= 2; ++oz)
    #pragma unroll
    for (int oy = -2; oy <= 2; ++oy)
    #pragma unroll
    for (int ox = -2; ox <= 2; ++ox) {
        const int s2 = oz * oz + oy * oy + ox * ox;
        if (s2 == 0 || s2 > 6) continue;
        CONTRIB2(c + oz * HXY + oy * HX + ox);
    }

    // Excluded shifts (s^2 >= 8) only matter via "contact with empty cell",
    // which needs |own pos| < 2 AND own occupied -> only the (1,1,1) corner.
    {
        float X0, X1, Y0, Y1, Z0, Z1;
        unpk(Xp, X0, X1); unpk(Yp, Y0, Y1); unpk(Zp, Z0, Z1);
        float o0 = X0 * X0 + Y0 * Y0 + Z0 * Z0;
        float o1 = X1 * X1 + Y1 * Y1 + Z1 * Z1;
        bool q0 = (m0 != 0.0f) && (o0 < 4.0f);
        bool q1 = (m1 != 0.0f) && (o1 < 4.0f);
        if (q0 || q1) {
            #pragma unroll 1
            for (int oz = -2; oz <= 2; ++oz)
            #pragma unroll 1
            for (int oy = -2; oy <= 2; ++oy)
            #pragma unroll 1
            for (int ox = -2; ox <= 2; ++ox) {
                int s2 = oz * oz + oy * oy + ox * ox;
                if (s2 <= 6) continue;
                CONTRIB2(c + oz * HXY + oy * HX + ox);
            }
        }
    }

    // Epilogue per half (scalar; once per cell, negligible)
    float X0, X1, Y0, Y1, Z0, Z1, VX0, VX1, VY0, VY1, VZ0, VZ1;
    float fx0, fx1, fy0, fy1, fz0, fz1;
    unpk(Xp, X0, X1);  unpk(Yp, Y0, Y1);  unpk(Zp, Z0, Z1);
    unpk(VXp, VX0, VX1); unpk(VYp, VY0, VY1); unpk(VZp, VZ0, VZ1);
    unpk(fxp, fx0, fx1); unpk(fyp, fy0, fy1); unpk(fzp, fz0, fz1);

    finish_half(X0, Y0, Z0, VX0, VY0, VZ0, m0, fx0, fy0, fz0, ETA, out);
    finish_half(X1, Y1, Z1, VX1, VY1, VZ1, m1, fx1, fy1, fz1, ETA, out);
}

extern "C" void kernel_launch(void* const* d_in, const int* in_sizes, int n_in,
                              void* d_out, int out_size)
{
    const float* xg  = (const float*)d_in[0];
    const float* yg  = (const float*)d_in[1];
    const float* zg  = (const float*)d_in[2];
    const float* vxg = (const float*)d_in[3];
    const float* vyg = (const float*)d_in[4];
    const float* vzg = (const float*)d_in[5];
    const float* mg  = (const float*)d_in[6];
    float* out = (float*)d_out;

    // Reference's "zero at lo" collapses to: zero everything, scatter at ln.
    cudaMemsetAsync(d_out, 0, (size_t)out_size * sizeof(float), 0);

    double alpha = -log(0.7) / M_PI;
    double gamma = alpha / sqrt(alpha * alpha + 1.0);
    float  eta   = (float)(2.0 * gamma * sqrt(500000.0 * 1.0));

    const size_t smem = 6 * HTOT2 * sizeof(float2);  // 110592 B
    cudaFuncSetAttribute(dem_step, cudaFuncAttributeMaxDynamicSharedMemorySize, (int)smem);

    dim3 block(TXD, TYD, TZH);
    dim3 grid(DS / TXD, DS / TYD, DS / TZD);   // 4 x 32 x 16 = 2048 blocks
    dem_step<<<grid, block, smem>>>(xg, yg, zg, vxg, vyg, vzg, mg, out, eta);
}

// round 3
// speedup vs baseline: 1.6590x; 1.6590x over previous
#include <cuda_runtime.h>
#include <math.h>

#define DS   128
#define DSM  (DS - 1)
#define D3   (DS * DS * DS)

#define TXD  32
#define TYD  4
#define TZD  4
#define NTHR (TXD * TYD * TZD)   // 512

#define HX   36
#define HY   8
#define HZ   8
#define HXY  (HX * HY)
#define HTOT (HXY * HZ)          // 2304

struct SM {
    float2         xy[HTOT];     // (x,y) interleaved
    float2         vxy[HTOT];    // (vx,vy) interleaved
    float          z[HTOT];
    float          vz[HTOT];
    unsigned short list[NTHR];   // halo-space indices of occupied cells
    int            cnt;
};

__device__ __forceinline__ float fast_rsqrt(float x) {
    float r; asm("rsqrt.approx.f32 %0, %1;" : "=f"(r) : "f"(x)); return r;
}

// Stencil contribution at halo offset o.  coef = KN*(dist-2)/dist + ETA*vn/dist
//   = KN - 2KN*rcd + ETA*vnu*rcd^2   with rcd = rsqrt(sq), vnu = dv.d
// sq >= 0.09 whenever own cell is occupied (see notes), so no clamps needed.
#define CONTRIB(o)                                                            \
    {                                                                         \
        float2 nxy = S->xy[(o)];                                              \
        float  nz  = S->z[(o)];                                               \
        float dx = X - nxy.x, dy = Y - nxy.y, dz = Z - nz;                    \
        float sq = dx * dx + dy * dy + dz * dz;                               \
        if (sq < 4.0f) {                                                      \
            float2 nv  = S->vxy[(o)];                                         \
            float  nvz = S->vz[(o)];                                          \
            float rcd = fast_rsqrt(sq);                                       \
            float vnu = (VX - nv.x) * dx + (VY - nv.y) * dy + (VZ - nvz) * dz;\
            float coef = fmaf(ETA * vnu, rcd * rcd,                           \
                              fmaf(-1000000.0f, rcd, 500000.0f));             \
            fx = fmaf(coef, dx, fx);                                          \
            fy = fmaf(coef, dy, fy);                                          \
            fz = fmaf(coef, dz, fz);                                          \
        }                                                                     \
    }

__global__ __launch_bounds__(NTHR, 2) void dem_step(
    const float* __restrict__ xg,  const float* __restrict__ yg,
    const float* __restrict__ zg,  const float* __restrict__ vxg,
    const float* __restrict__ vyg, const float* __restrict__ vzg,
    const float* __restrict__ mg,  float* __restrict__ out, float ETA)
{
    extern __shared__ char smraw[];
    SM* S = (SM*)smraw;

    const int x0 = blockIdx.x * TXD;
    const int y0 = blockIdx.y * TYD;
    const int z0 = blockIdx.z * TZD;
    const int tid = threadIdx.x + TXD * (threadIdx.y + TYD * threadIdx.z);

    if (tid == 0) S->cnt = 0;

    // Cooperative halo fill (periodic wrap: & 127)
    for (int i = tid; i < HTOT; i += NTHR) {
        int lx = i % HX;
        int t  = i / HX;
        int ly = t % HY;
        int lz = t / HY;
        int gx = (x0 + lx - 2) & DSM;
        int gy = (y0 + ly - 2) & DSM;
        int gz = (z0 + lz - 2) & DSM;
        int g  = (gz << 14) | (gy << 7) | gx;
        S->xy[i]  = make_float2(__ldg(xg + g),  __ldg(yg + g));
        S->vxy[i] = make_float2(__ldg(vxg + g), __ldg(vyg + g));
        S->z[i]   = __ldg(zg + g);
        S->vz[i]  = __ldg(vzg + g);
    }

    const int gx = x0 + threadIdx.x;
    const int gy = y0 + threadIdx.y;
    const int gz = z0 + threadIdx.z;
    const float m = __ldg(mg + ((gz << 14) | (gy << 7) | gx));
    const int   c = (threadIdx.z + 2) * HXY + (threadIdx.y + 2) * HX + (threadIdx.x + 2);

    __syncthreads();

    // Warp-aggregated compaction of occupied cells into S->list
    unsigned bal = __ballot_sync(0xFFFFFFFFu, m != 0.0f);
    int base = 0;
    if ((tid & 31) == 0 && bal) base = atomicAdd(&S->cnt, __popc(bal));
    base = __shfl_sync(0xFFFFFFFFu, base, 0);
    if (m != 0.0f) {
        int rank = __popc(bal & ((1u << (tid & 31)) - 1u));
        S->list[base + rank] = (unsigned short)c;
    }
    __syncthreads();

    const int cnt = S->cnt;
    const float KN = 500000.0f;

    for (int i = tid; i < cnt; i += NTHR) {
        const int cc = S->list[i];
        const float2 XYp  = S->xy[cc];
        const float2 VXYp = S->vxy[cc];
        const float X = XYp.x,  Y = XYp.y,  Z  = S->z[cc];
        const float VX = VXYp.x, VY = VXYp.y, VZ = S->vz[cc];

        float fx = 0.0f, fy = 0.0f, fz = 0.0f;

        // 80 shifts with s^2 in [1,6] — the only shifts where two occupied
        // particles (pos = idx +- 0.2) can have dist < 2. Fully unrolled.
        #pragma unroll
        for (int oz = -2; oz <= 2; ++oz)
        #pragma unroll
        for (int oy = -2; oy <= 2; ++oy)
        #pragma unroll
        for (int ox = -2; ox <= 2; ++ox) {
            const int s2 = oz * oz + oy * oy + ox * ox;
            if (s2 == 0 || s2 > 6) continue;
            CONTRIB(cc + oz * HXY + oy * HX + ox);
        }

        // Excluded shifts (s^2 >= 8) only matter via "contact with empty
        // cell" (rolled value 0), requiring |own pos| < 2 — origin corner only.
        if (X * X + Y * Y + Z * Z < 4.0f) {
            #pragma unroll 1
            for (int oz = -2; oz <= 2; ++oz)
            #pragma unroll 1
            for (int oy = -2; oy <= 2; ++oy)
            #pragma unroll 1
            for (int ox = -2; ox <= 2; ++ox) {
                int s2 = oz * oz + oy * oy + ox * ox;
                if (s2 <= 6) continue;
                CONTRIB(cc + oz * HXY + oy * HX + ox);
            }
        }

        // Boundary overlap forces (mask == 1 for list entries)
        float bl = (X != 0.0f && X < 1.0f) ? 1.0f : 0.0f;
        float br = (X > 126.0f) ? 1.0f : 0.0f;
        float bb = (Y != 0.0f && Y < 1.0f) ? 1.0f : 0.0f;
        float bt = (Y > 126.0f) ? 1.0f : 0.0f;
        float bf = (Z != 0.0f && Z < 1.0f) ? 1.0f : 0.0f;
        float bk = (Z > 126.0f) ? 1.0f : 0.0f;
        float fxb = KN * bl * (1.0f - X) - KN * br * (X - 126.0f) - ETA * VX * (bl + br);
        float fyb = KN * bb * (1.0f - Y) - KN * bt * (Y - 126.0f) - ETA * VY * (bb + bt);
        float fzb = KN * bf * (1.0f - Z) - KN * bk * (Z - 126.0f) - ETA * VZ * (bf + bk);

        float vxn = VX + 1e-4f * (-fx + fxb);
        float vyn = VY + 1e-4f * (-9.8f - fy + fyb);
        float vzn = VZ + 1e-4f * (-fz + fzb);
        float xn = X + 1e-4f * vxn;
        float yn = Y + 1e-4f * vyn;
        float zn = Z + 1e-4f * vzn;

        // Cell-list relocation (round half-even like jnp.round; comp==0
        // invalid; out-of-range dropped).
        int cx = __float2int_rn(xn);
        int cy = __float2int_rn(yn);
        int cz = __float2int_rn(zn);
        if (cx >= 1 && cx <= 127 && cy >= 1 && cy <= 127 && cz >= 1 && cz <= 127) {
            int l = (cz << 14) | (cy << 7) | cx;
            out[l]          = xn;
            out[D3 + l]     = yn;
            out[2 * D3 + l] = zn;
            out[3 * D3 + l] = vxn;
            out[4 * D3 + l] = vyn;
            out[5 * D3 + l] = vzn;
            out[6 * D3 + l] = 1.0f;
        }
    }
}

extern "C" void kernel_launch(void* const* d_in, const int* in_sizes, int n_in,
                              void* d_out, int out_size)
{
    const float* xg  = (const float*)d_in[0];
    const float* yg  = (const float*)d_in[1];
    const float* zg  = (const float*)d_in[2];
    const float* vxg = (const float*)d_in[3];
    const float* vyg = (const float*)d_in[4];
    const float* vzg = (const float*)d_in[5];
    const float* mg  = (const float*)d_in[6];
    float* out = (float*)d_out;

    // Reference's "zero at lo" collapses to: zero everything, scatter at ln.
    cudaMemsetAsync(d_out, 0, (size_t)out_size * sizeof(float), 0);

    double alpha = -log(0.7) / M_PI;
    double gamma = alpha / sqrt(alpha * alpha + 1.0);
    float  eta   = (float)(2.0 * gamma * sqrt(500000.0 * 1.0));

    const size_t smem = sizeof(SM);   // ~56.3 KB
    cudaFuncSetAttribute(dem_step, cudaFuncAttributeMaxDynamicSharedMemorySize, (int)smem);

    dim3 block(TXD, TYD, TZD);
    dim3 grid(DS / TXD, DS / TYD, DS / TZD);   // 4 x 32 x 32
    dem_step<<<grid, block, smem>>>(xg, yg, zg, vxg, vyg, vzg, mg, out, eta);
}

// round 4
// speedup vs baseline: 2.1478x; 1.2946x over previous
#include <cuda_runtime.h>
#include <math.h>

#define DS   128
#define DSM  (DS - 1)
#define D3   (DS * DS * DS)

// Tile: 32 x 8 x 4 real cells = 1024; 512 threads.
#define TXD   32
#define TYD   8
#define TZD   4
#define CELLS (TXD * TYD * TZD)  // 1024
#define NTHR  512

#define HX   36
#define HY   12
#define HZ   8
#define HXY  (HX * HY)           // 432
#define HTOT (HXY * HZ)          // 3456

struct SM {
    float2         xy[HTOT];     // (x,y) interleaved
    float2         vxy[HTOT];    // (vx,vy) interleaved
    float          z[HTOT];
    float          vz[HTOT];
    unsigned short list[CELLS];  // halo-space indices of occupied cells
    int            cnt;
};

__device__ __forceinline__ float fast_rsqrt(float x) {
    float r; asm("rsqrt.approx.f32 %0, %1;" : "=f"(r) : "f"(x)); return r;
}

// Stencil contribution at halo offset o.  coef = KN*(dist-2)/dist + ETA*vn/dist
//   = KN - 2KN*rcd + ETA*vnu*rcd^2   with rcd = rsqrt(sq), vnu = dv.d
#define CONTRIB(o)                                                            \
    {                                                                         \
        float2 nxy = S->xy[(o)];                                              \
        float  nz  = S->z[(o)];                                               \
        float dx = X - nxy.x, dy = Y - nxy.y, dz = Z - nz;                    \
        float sq = dx * dx + dy * dy + dz * dz;                               \
        if (sq < 4.0f) {                                                      \
            float2 nv  = S->vxy[(o)];                                         \
            float  nvz = S->vz[(o)];                                          \
            float rcd = fast_rsqrt(sq);                                       \
            float vnu = (VX - nv.x) * dx + (VY - nv.y) * dy + (VZ - nvz) * dz;\
            float coef = fmaf(ETA * vnu, rcd * rcd,                           \
                              fmaf(-1000000.0f, rcd, 500000.0f));             \
            fx = fmaf(coef, dx, fx);                                          \
            fy = fmaf(coef, dy, fy);                                          \
            fz = fmaf(coef, dz, fz);                                          \
        }                                                                     \
    }

__global__ __launch_bounds__(NTHR, 2) void dem_step(
    const float* __restrict__ xg,  const float* __restrict__ yg,
    const float* __restrict__ zg,  const float* __restrict__ vxg,
    const float* __restrict__ vyg, const float* __restrict__ vzg,
    const float* __restrict__ mg,  float* __restrict__ out, float ETA)
{
    extern __shared__ char smraw[];
    SM* S = (SM*)smraw;

    const int x0 = blockIdx.x * TXD;
    const int y0 = blockIdx.y * TYD;
    const int z0 = blockIdx.z * TZD;
    const int tid = threadIdx.x;

    if (tid == 0) S->cnt = 0;

    // Cooperative halo fill (periodic wrap: & 127)
    for (int i = tid; i < HTOT; i += NTHR) {
        int lx = i % HX;
        int t  = i / HX;
        int ly = t % HY;
        int lz = t / HY;
        int gx = (x0 + lx - 2) & DSM;
        int gy = (y0 + ly - 2) & DSM;
        int gz = (z0 + lz - 2) & DSM;
        int g  = (gz << 14) | (gy << 7) | gx;
        S->xy[i]  = make_float2(__ldg(xg + g),  __ldg(yg + g));
        S->vxy[i] = make_float2(__ldg(vxg + g), __ldg(vyg + g));
        S->z[i]   = __ldg(zg + g);
        S->vz[i]  = __ldg(vzg + g);
    }
    __syncthreads();

    // Warp-aggregated compaction: each thread inspects 2 cells of the tile.
    #pragma unroll
    for (int half = 0; half < CELLS / NTHR; ++half) {
        const int i  = tid + half * NTHR;        // tile-linear cell id
        const int lx = i & 31;
        const int ly = (i >> 5) & 7;
        const int lz = i >> 8;
        const float m = __ldg(mg + (((z0 + lz) << 14) | ((y0 + ly) << 7) | (x0 + lx)));
        const int c   = (lz + 2) * HXY + (ly + 2) * HX + (lx + 2);
        unsigned bal = __ballot_sync(0xFFFFFFFFu, m != 0.0f);
        int base = 0;
        if ((tid & 31) == 0 && bal) base = atomicAdd(&S->cnt, __popc(bal));
        base = __shfl_sync(0xFFFFFFFFu, base, 0);
        if (m != 0.0f) {
            int rank = __popc(bal & ((1u << (tid & 31)) - 1u));
            S->list[base + rank] = (unsigned short)c;
        }
    }
    __syncthreads();

    const int cnt = S->cnt;
    const float KN = 500000.0f;

    for (int i = tid; i < cnt; i += NTHR) {
        const int cc = S->list[i];
        const float2 XYp  = S->xy[cc];
        const float2 VXYp = S->vxy[cc];
        const float X = XYp.x,  Y = XYp.y,  Z  = S->z[cc];
        const float VX = VXYp.x, VY = VXYp.y, VZ = S->vz[cc];

        float fx = 0.0f, fy = 0.0f, fz = 0.0f;

        // 80 shifts with s^2 in [1,6] — the only shifts where two occupied
        // particles (pos = idx +- 0.2) can have dist < 2. Fully unrolled.
        #pragma unroll
        for (int oz = -2; oz <= 2; ++oz)
        #pragma unroll
        for (int oy = -2; oy <= 2; ++oy)
        #pragma unroll
        for (int ox = -2; ox <= 2; ++ox) {
            const int s2 = oz * oz + oy * oy + ox * ox;
            if (s2 == 0 || s2 > 6) continue;
            CONTRIB(cc + oz * HXY + oy * HX + ox);
        }

        // Excluded shifts (s^2 >= 8) only matter via "contact with empty
        // cell" (rolled value 0), requiring |own pos| < 2 — origin corner only.
        if (X * X + Y * Y + Z * Z < 4.0f) {
            #pragma unroll 1
            for (int oz = -2; oz <= 2; ++oz)
            #pragma unroll 1
            for (int oy = -2; oy <= 2; ++oy)
            #pragma unroll 1
            for (int ox = -2; ox <= 2; ++ox) {
                int s2 = oz * oz + oy * oy + ox * ox;
                if (s2 <= 6) continue;
                CONTRIB(cc + oz * HXY + oy * HX + ox);
            }
        }

        // Boundary overlap forces (mask == 1 for list entries)
        float bl = (X != 0.0f && X < 1.0f) ? 1.0f : 0.0f;
        float br = (X > 126.0f) ? 1.0f : 0.0f;
        float bb = (Y != 0.0f && Y < 1.0f) ? 1.0f : 0.0f;
        float bt = (Y > 126.0f) ? 1.0f : 0.0f;
        float bf = (Z != 0.0f && Z < 1.0f) ? 1.0f : 0.0f;
        float bk = (Z > 126.0f) ? 1.0f : 0.0f;
        float fxb = KN * bl * (1.0f - X) - KN * br * (X - 126.0f) - ETA * VX * (bl + br);
        float fyb = KN * bb * (1.0f - Y) - KN * bt * (Y - 126.0f) - ETA * VY * (bb + bt);
        float fzb = KN * bf * (1.0f - Z) - KN * bk * (Z - 126.0f) - ETA * VZ * (bf + bk);

        float vxn = VX + 1e-4f * (-fx + fxb);
        float vyn = VY + 1e-4f * (-9.8f - fy + fyb);
        float vzn = VZ + 1e-4f * (-fz + fzb);
        float xn = X + 1e-4f * vxn;
        float yn = Y + 1e-4f * vyn;
        float zn = Z + 1e-4f * vzn;

        // Cell-list relocation (round half-even like jnp.round; comp==0
        // invalid; out-of-range dropped).
        int cx = __float2int_rn(xn);
        int cy = __float2int_rn(yn);
        int cz = __float2int_rn(zn);
        if (cx >= 1 && cx <= 127 && cy >= 1 && cy <= 127 && cz >= 1 && cz <= 127) {
            int l = (cz << 14) | (cy << 7) | cx;
            out[l]          = xn;
            out[D3 + l]     = yn;
            out[2 * D3 + l] = zn;
            out[3 * D3 + l] = vxn;
            out[4 * D3 + l] = vyn;
            out[5 * D3 + l] = vzn;
            out[6 * D3 + l] = 1.0f;
        }
    }
}

extern "C" void kernel_launch(void* const* d_in, const int* in_sizes, int n_in,
                              void* d_out, int out_size)
{
    const float* xg  = (const float*)d_in[0];
    const float* yg  = (const float*)d_in[1];
    const float* zg  = (const float*)d_in[2];
    const float* vxg = (const float*)d_in[3];
    const float* vyg = (const float*)d_in[4];
    const float* vzg = (const float*)d_in[5];
    const float* mg  = (const float*)d_in[6];
    float* out = (float*)d_out;

    // Reference's "zero at lo" collapses to: zero everything, scatter at ln.
    cudaMemsetAsync(d_out, 0, (size_t)out_size * sizeof(float), 0);

    double alpha = -log(0.7) / M_PI;
    double gamma = alpha / sqrt(alpha * alpha + 1.0);
    float  eta   = (float)(2.0 * gamma * sqrt(500000.0 * 1.0));

    const size_t smem = sizeof(SM);   // ~85 KB
    cudaFuncSetAttribute(dem_step, cudaFuncAttributeMaxDynamicSharedMemorySize, (int)smem);

    dim3 block(NTHR, 1, 1);
    dim3 grid(DS / TXD, DS / TYD, DS / TZD);   // 4 x 16 x 32 = 2048 blocks
    dem_step<<<grid, block, smem>>>(xg, yg, zg, vxg, vyg, vzg, mg, out, eta);
}